// round 16
// baseline (speedup 1.0000x reference)
#include <cuda_runtime.h>
#include <cuda_fp16.h>
#include <stdint.h>

#define N_NODES 50000
#define N_EDGES 400000
#define F_IN    128
#define F_HID   512
#define F_OUT   250
#define F_OUT_P 256   // padded t2 stride

#define SCAN_B  256
#define SCAN_NB ((N_NODES + SCAN_B - 1) / SCAN_B)   // 196

// ---------------- scratch (static __device__ — no allocation) ----------------
__device__ int   g_is32;
__device__ int   g_total;                  // CSR allocation counter
__device__ int   g_src[N_EDGES];
__device__ int   g_dst[N_EDGES];
__device__ int   g_edeg[N_NODES];          // edge-only in-degree
__device__ float g_dinv[N_NODES];
__device__ int   g_rowbeg[N_NODES];        // CSR range start (unordered alloc)
__device__ int   g_cursor[N_NODES];
__device__ int   g_csrc[N_EDGES];          // CSR-by-dst: source node ids
__device__ __half g_ax [(size_t)N_NODES * F_IN];     // A_hat·x, fp16
__device__ __half g_h1 [(size_t)N_NODES * F_HID];    // relu layer-1, fp16
__device__ __half g_t2 [(size_t)N_NODES * F_OUT_P];  // h1·W2, fp16 (padded)
__device__ __half g_w1t[(size_t)F_HID * F_IN];       // W1^T [512][128] fp16
__device__ __half g_w2t[(size_t)F_OUT_P * F_HID];    // W2^T [256][512], rows>=250 zero

// bit-cast helpers
__device__ __forceinline__ uint32_t h2_as_u32(__half2 h) {
    union { __half2 h; uint32_t u; } c; c.h = h; return c.u;
}
__device__ __forceinline__ __half2 u32_as_h2(uint32_t u) {
    union { uint32_t u; __half2 h; } c; c.u = u; return c.h;
}

// ---------------- detect dtype (block 0) + init (all blocks) -----------------
__global__ void detect_init_kernel(const void* __restrict__ ei_raw) {
    int i = blockIdx.x * blockDim.x + threadIdx.x;
    if (i < N_NODES) g_edeg[i] = 0;
    if (i == 0) g_total = 0;
    if (blockIdx.x == 0) {
        const long long* p = (const long long*)ei_raw;
        int bad = 0;
        for (int k = threadIdx.x; k < 4096; k += blockDim.x) {
            long long v = p[k];
            if (v < 0 || v >= N_NODES) bad = 1;
        }
        int any = __syncthreads_or(bad);
        if (threadIdx.x == 0) g_is32 = any;   // 1 => int32 layout
    }
}
__global__ void convert_count_kernel(const void* __restrict__ ei_raw) {
    int e = blockIdx.x * blockDim.x + threadIdx.x;
    if (e >= N_EDGES) return;
    int s, d;
    if (g_is32) {
        const int* p = (const int*)ei_raw;
        s = p[e]; d = p[N_EDGES + e];
    } else {
        const long long* p = (const long long*)ei_raw;
        s = (int)p[e]; d = (int)p[N_EDGES + e];
    }
    g_src[e] = s; g_dst[e] = d;
    atomicAdd(&g_edeg[d], 1);
}

// ---------------- CSR alloc: ONE kernel (block scan + atomic block base) -----
__global__ void alloc_scan_kernel() {
    __shared__ int sh[SCAN_B];
    __shared__ int base_s;
    int i = blockIdx.x * SCAN_B + threadIdx.x;
    int v = (i < N_NODES) ? g_edeg[i] : 0;
    sh[threadIdx.x] = v;
    __syncthreads();
    for (int o = 1; o < SCAN_B; o <<= 1) {
        int t = (threadIdx.x >= o) ? sh[threadIdx.x - o] : 0;
        __syncthreads();
        sh[threadIdx.x] += t;
        __syncthreads();
    }
    if (threadIdx.x == SCAN_B - 1)
        base_s = atomicAdd(&g_total, sh[threadIdx.x]);   // block base, unordered
    __syncthreads();
    if (i < N_NODES) {
        int excl = base_s + sh[threadIdx.x] - v;
        g_rowbeg[i] = excl;
        g_cursor[i] = excl;
        g_dinv[i] = rsqrtf((float)(v + 1));   // + self-loop
    }
}
__global__ void fill_kernel() {
    int e = blockIdx.x * blockDim.x + threadIdx.x;
    if (e >= N_EDGES) return;
    int d = g_dst[e];
    int p = atomicAdd(&g_cursor[d], 1);
    g_csrc[p] = g_src[e];
}

// ---------------- weight transpose + fp16 convert ----------------------------
#define W1T_ELEMS (F_HID * F_IN)
#define W2T_ELEMS (F_OUT_P * F_HID)
__global__ void convert_w_kernel(const float* __restrict__ W1, const float* __restrict__ W2) {
    int idx = blockIdx.x * blockDim.x + threadIdx.x;
    if (idx < W1T_ELEMS) {
        int n = idx / F_IN, k = idx % F_IN;
        g_w1t[idx] = __float2half_rn(W1[(size_t)k * F_HID + n]);
    } else if (idx < W1T_ELEMS + W2T_ELEMS) {
        int j = idx - W1T_ELEMS;
        int n = j / F_HID, k = j % F_HID;
        float v = (n < F_OUT) ? W2[(size_t)k * F_OUT + n] : 0.f;
        g_w2t[j] = __float2half_rn(v);
    }
}

// ---------------- layer-1: CSR gather (x2 unrolled) -> fp16, warp per node ---
__global__ __launch_bounds__(256)
void gather1_kernel(const float* __restrict__ x) {
    int node = blockIdx.x * 8 + (threadIdx.x >> 5);
    if (node >= N_NODES) return;
    int lane = threadIdx.x & 31;
    float di = g_dinv[node];
    const float4* x4 = (const float4*)x;
    float4 v = x4[(size_t)node * 32 + lane];
    float ws = di * di;
    float4 acc = make_float4(ws*v.x, ws*v.y, ws*v.z, ws*v.w);
    int beg = g_rowbeg[node], end = beg + g_edeg[node];
    int j = beg;
    for (; j + 1 < end; j += 2) {
        int s0 = g_csrc[j], s1 = g_csrc[j + 1];
        float w0 = g_dinv[s0] * di, w1 = g_dinv[s1] * di;
        float4 u0 = x4[(size_t)s0 * 32 + lane];
        float4 u1 = x4[(size_t)s1 * 32 + lane];
        acc.x += w0*u0.x + w1*u1.x; acc.y += w0*u0.y + w1*u1.y;
        acc.z += w0*u0.z + w1*u1.z; acc.w += w0*u0.w + w1*u1.w;
    }
    if (j < end) {
        int s = g_csrc[j];
        float w = g_dinv[s] * di;
        float4 u = x4[(size_t)s * 32 + lane];
        acc.x += w*u.x; acc.y += w*u.y; acc.z += w*u.z; acc.w += w*u.w;
    }
    uint32_t p0 = h2_as_u32(__floats2half2_rn(acc.x, acc.y));
    uint32_t p1 = h2_as_u32(__floats2half2_rn(acc.z, acc.w));
    *(uint2*)&g_ax[(size_t)node * F_IN + lane * 4] = make_uint2(p0, p1);
}

// ---------------- warp-MMA fp16 GEMM (single product), 128x128 block ---------
#define SPAD 40
#define TILE_B  (128 * SPAD * 2)       // 10240 B
#define STAGE_B (2 * TILE_B)           // 20480 B (A + B tiles only)
#define GSMEM   (2 * STAGE_B)          // 40960 B

__device__ __forceinline__ uint32_t smem_u32(const void* p) {
    uint32_t a;
    asm("{ .reg .u64 t; cvta.to.shared.u64 t, %1; cvt.u32.u64 %0, t; }" : "=r"(a) : "l"(p));
    return a;
}
#define CP_ASYNC16(dst, src, n) \
    asm volatile("cp.async.cg.shared.global [%0], [%1], 16, %2;" :: "r"(dst), "l"(src), "r"(n))
#define CP_COMMIT() asm volatile("cp.async.commit_group;" ::: "memory")
#define LDSM4(r0, r1, r2, r3, addr) \
    asm volatile("ldmatrix.sync.aligned.m8n8.x4.shared.b16 {%0,%1,%2,%3}, [%4];" \
        : "=r"(r0), "=r"(r1), "=r"(r2), "=r"(r3) : "r"(addr) : "memory")

__device__ __forceinline__ void mma_f16(float c[4], const uint32_t a[4],
                                        uint32_t b0, uint32_t b1) {
    asm volatile(
        "mma.sync.aligned.m16n8k16.row.col.f32.f16.f16.f32 "
        "{%0,%1,%2,%3}, {%4,%5,%6,%7}, {%8,%9}, {%0,%1,%2,%3};"
        : "+f"(c[0]), "+f"(c[1]), "+f"(c[2]), "+f"(c[3])
        : "r"(a[0]), "r"(a[1]), "r"(a[2]), "r"(a[3]), "r"(b0), "r"(b1));
}

template<int SEL, int KTOT>
__global__ __launch_bounds__(256, 2)
void gemm_mma_kernel(const float* __restrict__ bias) {
    const __half* A  = (SEL == 0) ? g_ax  : g_h1;
    const __half* Bt = (SEL == 0) ? g_w1t : g_w2t;

    extern __shared__ char smem[];
    const uint32_t sb = smem_u32(smem);

    const int tid  = threadIdx.x;
    const int lane = tid & 31, wid = tid >> 5;
    const int wm = (wid >> 2) * 64;
    const int wn = (wid & 3) * 32;
    const int g  = lane >> 2, tg = lane & 3;
    const int m0 = blockIdx.y * 128, n0 = blockIdx.x * 128;

    const uint32_t a_base = (uint32_t)((wm + (lane & 15)) * (SPAD * 2) + ((lane >> 4) * 8) * 2);
    const uint32_t b_base = (uint32_t)((wn + (lane >> 4) * 8 + (lane & 7)) * (SPAD * 2)
                                       + (((lane >> 3) & 1) * 8) * 2);

    float acc[4][4][4];
    #pragma unroll
    for (int i = 0; i < 4; i++)
        #pragma unroll
        for (int j = 0; j < 4; j++)
            #pragma unroll
            for (int q = 0; q < 4; q++) acc[i][j][q] = 0.f;

    auto load_stage = [&](int stage, int kk) {
        const uint32_t stb = sb + stage * STAGE_B;
        #pragma unroll
        for (int i = tid; i < 512; i += 256) {
            int r = i >> 2, c = i & 3;
            uint32_t ro = (uint32_t)(r * (SPAD * 2) + c * 16);
            size_t gA = (size_t)(m0 + r) * KTOT + kk + c * 8;
            int okA = ((m0 + r) < N_NODES) ? 16 : 0;
            CP_ASYNC16(stb + 0 * TILE_B + ro, A  + gA, okA);
            size_t gB = (size_t)(n0 + r) * KTOT + kk + c * 8;
            CP_ASYNC16(stb + 1 * TILE_B + ro, Bt + gB, 16);
        }
        CP_COMMIT();
    };

    constexpr int KB = KTOT / 32;
    load_stage(0, 0);

    #pragma unroll 1
    for (int kb = 0; kb < KB; kb++) {
        if (kb + 1 < KB) {
            load_stage((kb + 1) & 1, (kb + 1) * 32);
            asm volatile("cp.async.wait_group 1;" ::: "memory");
        } else {
            asm volatile("cp.async.wait_group 0;" ::: "memory");
        }
        __syncthreads();

        const uint32_t stb = sb + (kb & 1) * STAGE_B;
        #pragma unroll
        for (int ks = 0; ks < 2; ks++) {
            const uint32_t kby = ks * 32;
            uint32_t af[4][4], bf[2][4];
            #pragma unroll
            for (int mi = 0; mi < 4; mi++) {
                uint32_t ao = stb + a_base + mi * (16 * SPAD * 2) + kby;
                LDSM4(af[mi][0], af[mi][1], af[mi][2], af[mi][3], ao + 0 * TILE_B);
            }
            #pragma unroll
            for (int pr = 0; pr < 2; pr++) {
                uint32_t bo = stb + b_base + pr * (16 * SPAD * 2) + kby;
                LDSM4(bf[pr][0], bf[pr][1], bf[pr][2], bf[pr][3], bo + 1 * TILE_B);
            }
            #pragma unroll
            for (int mi = 0; mi < 4; mi++)
                #pragma unroll
                for (int ni = 0; ni < 4; ni++) {
                    const int pr = ni >> 1, sl = (ni & 1) * 2;
                    mma_f16(acc[mi][ni], af[mi], bf[pr][sl], bf[pr][sl + 1]);
                }
        }
        __syncthreads();
    }

    #pragma unroll
    for (int mi = 0; mi < 4; mi++) {
        #pragma unroll
        for (int half = 0; half < 2; half++) {
            int m = m0 + wm + mi * 16 + g + half * 8;
            if (m >= N_NODES) continue;
            #pragma unroll
            for (int ni = 0; ni < 4; ni++) {
                int col = n0 + wn + ni * 8 + tg * 2;
                float v0 = acc[mi][ni][half * 2 + 0];
                float v1 = acc[mi][ni][half * 2 + 1];
                if (SEL == 0) {
                    v0 = fmaxf(v0 + __ldg(&bias[col]),     0.f);
                    v1 = fmaxf(v1 + __ldg(&bias[col + 1]), 0.f);
                    *(uint32_t*)&g_h1[(size_t)m * F_HID + col] =
                        h2_as_u32(__floats2half2_rn(v0, v1));
                } else {
                    *(uint32_t*)&g_t2[(size_t)m * F_OUT_P + col] =
                        h2_as_u32(__floats2half2_rn(v0, v1));
                }
            }
        }
    }
}

// ---------------- layer-2: CSR gather over fp16 t2 + bias + relu -------------
// warp per node; lane handles 8 cols (one uint4 = 8 halves per row read).
__global__ __launch_bounds__(256)
void gather2_kernel(const float* __restrict__ b2, float* __restrict__ out) {
    int node = blockIdx.x * 8 + (threadIdx.x >> 5);
    if (node >= N_NODES) return;
    int lane = threadIdx.x & 31;
    float di = g_dinv[node];
    const uint4* t4 = (const uint4*)g_t2;        // 8 halves per uint4; 32/row
    float acc[8];
    {
        uint4 r = t4[(size_t)node * 32 + lane];
        float2 f0 = __half22float2(u32_as_h2(r.x));
        float2 f1 = __half22float2(u32_as_h2(r.y));
        float2 f2 = __half22float2(u32_as_h2(r.z));
        float2 f3 = __half22float2(u32_as_h2(r.w));
        float ws = di * di;
        acc[0] = ws*f0.x; acc[1] = ws*f0.y; acc[2] = ws*f1.x; acc[3] = ws*f1.y;
        acc[4] = ws*f2.x; acc[5] = ws*f2.y; acc[6] = ws*f3.x; acc[7] = ws*f3.y;
    }
    int beg = g_rowbeg[node], end = beg + g_edeg[node];
    int j = beg;
    for (; j + 1 < end; j += 2) {
        int s0 = g_csrc[j], s1 = g_csrc[j + 1];
        float w0 = g_dinv[s0] * di, w1 = g_dinv[s1] * di;
        uint4 r0 = t4[(size_t)s0 * 32 + lane];
        uint4 r1 = t4[(size_t)s1 * 32 + lane];
        float2 a0 = __half22float2(u32_as_h2(r0.x)), b0 = __half22float2(u32_as_h2(r0.y));
        float2 c0 = __half22float2(u32_as_h2(r0.z)), d0 = __half22float2(u32_as_h2(r0.w));
        float2 a1 = __half22float2(u32_as_h2(r1.x)), b1 = __half22float2(u32_as_h2(r1.y));
        float2 c1 = __half22float2(u32_as_h2(r1.z)), d1 = __half22float2(u32_as_h2(r1.w));
        acc[0] += w0*a0.x + w1*a1.x; acc[1] += w0*a0.y + w1*a1.y;
        acc[2] += w0*b0.x + w1*b1.x; acc[3] += w0*b0.y + w1*b1.y;
        acc[4] += w0*c0.x + w1*c1.x; acc[5] += w0*c0.y + w1*c1.y;
        acc[6] += w0*d0.x + w1*d1.x; acc[7] += w0*d0.y + w1*d1.y;
    }
    if (j < end) {
        int s = g_csrc[j];
        float w = g_dinv[s] * di;
        uint4 r = t4[(size_t)s * 32 + lane];
        float2 a = __half22float2(u32_as_h2(r.x)), b = __half22float2(u32_as_h2(r.y));
        float2 c = __half22float2(u32_as_h2(r.z)), d = __half22float2(u32_as_h2(r.w));
        acc[0] += w*a.x; acc[1] += w*a.y; acc[2] += w*b.x; acc[3] += w*b.y;
        acc[4] += w*c.x; acc[5] += w*c.y; acc[6] += w*d.x; acc[7] += w*d.y;
    }
    float* orow = out + (size_t)node * F_OUT;
    int c0i = lane * 8;
    #pragma unroll
    for (int q = 0; q < 8; q++) {
        int c = c0i + q;
        if (c < F_OUT) orow[c] = fmaxf(acc[q] + __ldg(&b2[c]), 0.f);
    }
}

// ---------------- launch ----------------
extern "C" void kernel_launch(void* const* d_in, const int* in_sizes, int n_in,
                              void* d_out, int out_size) {
    const float* x  = (const float*)d_in[0];
    const void*  ei = d_in[1];
    const float* W1 = (const float*)d_in[2];
    const float* b1 = (const float*)d_in[3];
    const float* W2 = (const float*)d_in[4];
    const float* b2 = (const float*)d_in[5];
    float* out = (float*)d_out;

    cudaFuncSetAttribute(gemm_mma_kernel<0, F_IN>,
                         cudaFuncAttributeMaxDynamicSharedMemorySize, GSMEM);
    cudaFuncSetAttribute(gemm_mma_kernel<1, F_HID>,
                         cudaFuncAttributeMaxDynamicSharedMemorySize, GSMEM);

    detect_init_kernel<<<SCAN_NB, 256>>>(ei);                      // 1
    convert_count_kernel<<<(N_EDGES + 255) / 256, 256>>>(ei);      // 2
    alloc_scan_kernel<<<SCAN_NB, SCAN_B>>>();                      // 3
    fill_kernel<<<(N_EDGES + 255) / 256, 256>>>();                 // 4
    convert_w_kernel<<<(W1T_ELEMS + W2T_ELEMS + 255) / 256, 256>>>(W1, W2);  // 5
    gather1_kernel<<<(N_NODES + 7) / 8, 256>>>(x);                 // 6
    {
        dim3 grid(F_HID / 128, (N_NODES + 127) / 128);             // 7: (4, 391)
        gemm_mma_kernel<0, F_IN><<<grid, 256, GSMEM>>>(b1);
    }
    {
        dim3 grid(F_OUT_P / 128, (N_NODES + 127) / 128);           // 8: (2, 391)
        gemm_mma_kernel<1, F_HID><<<grid, 256, GSMEM>>>(nullptr);
    }
    gather2_kernel<<<(N_NODES + 7) / 8, 256>>>(b2, out);           // 9
}

// round 17
// speedup vs baseline: 1.0377x; 1.0377x over previous
#include <cuda_runtime.h>
#include <cuda_fp16.h>
#include <stdint.h>

#define N_NODES 50000
#define N_EDGES 400000
#define F_IN    128
#define F_HID   512
#define F_OUT   250
#define F_OUT_P 256   // padded t2 stride

#define SCAN_B  256
#define SCAN_NB ((N_NODES + SCAN_B - 1) / SCAN_B)   // 196

#define W1T_ELEMS (F_HID * F_IN)       // 65536
#define W2T_ELEMS (F_OUT_P * F_HID)    // 131072
#define INIT_NB   (((W1T_ELEMS + W2T_ELEMS) + 255) / 256)   // 768 blocks

// ---------------- scratch (static __device__ — no allocation) ----------------
__device__ int   g_is32;
__device__ int   g_total;                  // CSR allocation counter
__device__ int   g_src[N_EDGES];
__device__ int   g_dst[N_EDGES];
__device__ int   g_eoff[N_EDGES];          // per-edge rank within dst bucket
__device__ int   g_edeg[N_NODES];          // edge-only in-degree
__device__ float g_dinv[N_NODES];
__device__ int   g_rowbeg[N_NODES];        // CSR range start (unordered alloc)
__device__ int   g_csrc[N_EDGES];          // CSR-by-dst: source node ids
__device__ __half g_ax [(size_t)N_NODES * F_IN];     // A_hat·x, fp16
__device__ __half g_h1 [(size_t)N_NODES * F_HID];    // relu layer-1, fp16
__device__ float  g_t2 [(size_t)N_NODES * F_OUT_P];  // h1·W2 fp32 (padded)
__device__ __half g_w1t[(size_t)F_HID * F_IN];       // W1^T [512][128] fp16
__device__ __half g_w2t[(size_t)F_OUT_P * F_HID];    // W2^T [256][512], rows>=250 zero

// bit-cast helper
__device__ __forceinline__ uint32_t h2_as_u32(__half2 h) {
    union { __half2 h; uint32_t u; } c; c.h = h; return c.u;
}

// ---------------- detect dtype + edeg init + weight convert (fused) ----------
__global__ void detect_init_kernel(const void* __restrict__ ei_raw,
                                   const float* __restrict__ W1,
                                   const float* __restrict__ W2) {
    int i = blockIdx.x * blockDim.x + threadIdx.x;
    if (i < N_NODES) g_edeg[i] = 0;
    if (i == 0) g_total = 0;
    // weight conversion (independent of edges)
    if (i < W1T_ELEMS) {
        int n = i / F_IN, k = i % F_IN;
        g_w1t[i] = __float2half_rn(W1[(size_t)k * F_HID + n]);
    } else if (i < W1T_ELEMS + W2T_ELEMS) {
        int j = i - W1T_ELEMS;
        int n = j / F_HID, k = j % F_HID;
        float v = (n < F_OUT) ? W2[(size_t)k * F_OUT + n] : 0.f;
        g_w2t[j] = __float2half_rn(v);
    }
    // dtype sniff (block 0 only)
    if (blockIdx.x == 0) {
        const long long* p = (const long long*)ei_raw;
        int bad = 0;
        for (int k = threadIdx.x; k < 4096; k += blockDim.x) {
            long long v = p[k];
            if (v < 0 || v >= N_NODES) bad = 1;
        }
        int any = __syncthreads_or(bad);
        if (threadIdx.x == 0) g_is32 = any;   // 1 => int32 layout
    }
}

// ---------------- convert + count; atomic return value = per-edge rank -------
__global__ void convert_count_kernel(const void* __restrict__ ei_raw) {
    int e = blockIdx.x * blockDim.x + threadIdx.x;
    if (e >= N_EDGES) return;
    int s, d;
    if (g_is32) {
        const int* p = (const int*)ei_raw;
        s = p[e]; d = p[N_EDGES + e];
    } else {
        const long long* p = (const long long*)ei_raw;
        s = (int)p[e]; d = (int)p[N_EDGES + e];
    }
    g_src[e] = s; g_dst[e] = d;
    g_eoff[e] = atomicAdd(&g_edeg[d], 1);
}

// ---------------- CSR alloc: ONE kernel (block scan + atomic block base) -----
__global__ void alloc_scan_kernel() {
    __shared__ int sh[SCAN_B];
    __shared__ int base_s;
    int i = blockIdx.x * SCAN_B + threadIdx.x;
    int v = (i < N_NODES) ? g_edeg[i] : 0;
    sh[threadIdx.x] = v;
    __syncthreads();
    for (int o = 1; o < SCAN_B; o <<= 1) {
        int t = (threadIdx.x >= o) ? sh[threadIdx.x - o] : 0;
        __syncthreads();
        sh[threadIdx.x] += t;
        __syncthreads();
    }
    if (threadIdx.x == SCAN_B - 1)
        base_s = atomicAdd(&g_total, sh[threadIdx.x]);   // block base, unordered
    __syncthreads();
    if (i < N_NODES) {
        g_rowbeg[i] = base_s + sh[threadIdx.x] - v;
        g_dinv[i] = rsqrtf((float)(v + 1));   // + self-loop
    }
}

// ---------------- fill: pure scatter, no atomics ------------------------------
__global__ void fill_kernel() {
    int e = blockIdx.x * blockDim.x + threadIdx.x;
    if (e >= N_EDGES) return;
    g_csrc[g_rowbeg[g_dst[e]] + g_eoff[e]] = g_src[e];
}

// ---------------- layer-1: CSR gather (x2 unrolled) -> fp16, warp per node ---
__global__ __launch_bounds__(256)
void gather1_kernel(const float* __restrict__ x) {
    int node = blockIdx.x * 8 + (threadIdx.x >> 5);
    if (node >= N_NODES) return;
    int lane = threadIdx.x & 31;
    float di = g_dinv[node];
    const float4* x4 = (const float4*)x;
    float4 v = x4[(size_t)node * 32 + lane];
    float ws = di * di;
    float4 acc = make_float4(ws*v.x, ws*v.y, ws*v.z, ws*v.w);
    int beg = g_rowbeg[node], end = beg + g_edeg[node];
    int j = beg;
    for (; j + 1 < end; j += 2) {
        int s0 = g_csrc[j], s1 = g_csrc[j + 1];
        float w0 = g_dinv[s0] * di, w1 = g_dinv[s1] * di;
        float4 u0 = x4[(size_t)s0 * 32 + lane];
        float4 u1 = x4[(size_t)s1 * 32 + lane];
        acc.x += w0*u0.x + w1*u1.x; acc.y += w0*u0.y + w1*u1.y;
        acc.z += w0*u0.z + w1*u1.z; acc.w += w0*u0.w + w1*u1.w;
    }
    if (j < end) {
        int s = g_csrc[j];
        float w = g_dinv[s] * di;
        float4 u = x4[(size_t)s * 32 + lane];
        acc.x += w*u.x; acc.y += w*u.y; acc.z += w*u.z; acc.w += w*u.w;
    }
    uint32_t p0 = h2_as_u32(__floats2half2_rn(acc.x, acc.y));
    uint32_t p1 = h2_as_u32(__floats2half2_rn(acc.z, acc.w));
    *(uint2*)&g_ax[(size_t)node * F_IN + lane * 4] = make_uint2(p0, p1);
}

// ---------------- warp-MMA fp16 GEMM (single product), 128x128 block ---------
#define SPAD 40
#define TILE_B  (128 * SPAD * 2)       // 10240 B
#define STAGE_B (2 * TILE_B)           // 20480 B (A + B tiles only)
#define GSMEM   (2 * STAGE_B)          // 40960 B

__device__ __forceinline__ uint32_t smem_u32(const void* p) {
    uint32_t a;
    asm("{ .reg .u64 t; cvta.to.shared.u64 t, %1; cvt.u32.u64 %0, t; }" : "=r"(a) : "l"(p));
    return a;
}
#define CP_ASYNC16(dst, src, n) \
    asm volatile("cp.async.cg.shared.global [%0], [%1], 16, %2;" :: "r"(dst), "l"(src), "r"(n))
#define CP_COMMIT() asm volatile("cp.async.commit_group;" ::: "memory")
#define LDSM4(r0, r1, r2, r3, addr) \
    asm volatile("ldmatrix.sync.aligned.m8n8.x4.shared.b16 {%0,%1,%2,%3}, [%4];" \
        : "=r"(r0), "=r"(r1), "=r"(r2), "=r"(r3) : "r"(addr) : "memory")

__device__ __forceinline__ void mma_f16(float c[4], const uint32_t a[4],
                                        uint32_t b0, uint32_t b1) {
    asm volatile(
        "mma.sync.aligned.m16n8k16.row.col.f32.f16.f16.f32 "
        "{%0,%1,%2,%3}, {%4,%5,%6,%7}, {%8,%9}, {%0,%1,%2,%3};"
        : "+f"(c[0]), "+f"(c[1]), "+f"(c[2]), "+f"(c[3])
        : "r"(a[0]), "r"(a[1]), "r"(a[2]), "r"(a[3]), "r"(b0), "r"(b1));
}

template<int SEL, int KTOT>
__global__ __launch_bounds__(256, 2)
void gemm_mma_kernel(const float* __restrict__ bias) {
    const __half* A  = (SEL == 0) ? g_ax  : g_h1;
    const __half* Bt = (SEL == 0) ? g_w1t : g_w2t;

    extern __shared__ char smem[];
    const uint32_t sb = smem_u32(smem);

    const int tid  = threadIdx.x;
    const int lane = tid & 31, wid = tid >> 5;
    const int wm = (wid >> 2) * 64;
    const int wn = (wid & 3) * 32;
    const int g  = lane >> 2, tg = lane & 3;
    const int m0 = blockIdx.y * 128, n0 = blockIdx.x * 128;

    const uint32_t a_base = (uint32_t)((wm + (lane & 15)) * (SPAD * 2) + ((lane >> 4) * 8) * 2);
    const uint32_t b_base = (uint32_t)((wn + (lane >> 4) * 8 + (lane & 7)) * (SPAD * 2)
                                       + (((lane >> 3) & 1) * 8) * 2);

    float acc[4][4][4];
    #pragma unroll
    for (int i = 0; i < 4; i++)
        #pragma unroll
        for (int j = 0; j < 4; j++)
            #pragma unroll
            for (int q = 0; q < 4; q++) acc[i][j][q] = 0.f;

    auto load_stage = [&](int stage, int kk) {
        const uint32_t stb = sb + stage * STAGE_B;
        #pragma unroll
        for (int i = tid; i < 512; i += 256) {
            int r = i >> 2, c = i & 3;
            uint32_t ro = (uint32_t)(r * (SPAD * 2) + c * 16);
            size_t gA = (size_t)(m0 + r) * KTOT + kk + c * 8;
            int okA = ((m0 + r) < N_NODES) ? 16 : 0;
            CP_ASYNC16(stb + 0 * TILE_B + ro, A  + gA, okA);
            size_t gB = (size_t)(n0 + r) * KTOT + kk + c * 8;
            CP_ASYNC16(stb + 1 * TILE_B + ro, Bt + gB, 16);
        }
        CP_COMMIT();
    };

    constexpr int KB = KTOT / 32;
    load_stage(0, 0);

    #pragma unroll 1
    for (int kb = 0; kb < KB; kb++) {
        if (kb + 1 < KB) {
            load_stage((kb + 1) & 1, (kb + 1) * 32);
            asm volatile("cp.async.wait_group 1;" ::: "memory");
        } else {
            asm volatile("cp.async.wait_group 0;" ::: "memory");
        }
        __syncthreads();

        const uint32_t stb = sb + (kb & 1) * STAGE_B;
        #pragma unroll
        for (int ks = 0; ks < 2; ks++) {
            const uint32_t kby = ks * 32;
            uint32_t af[4][4], bf[2][4];
            #pragma unroll
            for (int mi = 0; mi < 4; mi++) {
                uint32_t ao = stb + a_base + mi * (16 * SPAD * 2) + kby;
                LDSM4(af[mi][0], af[mi][1], af[mi][2], af[mi][3], ao + 0 * TILE_B);
            }
            #pragma unroll
            for (int pr = 0; pr < 2; pr++) {
                uint32_t bo = stb + b_base + pr * (16 * SPAD * 2) + kby;
                LDSM4(bf[pr][0], bf[pr][1], bf[pr][2], bf[pr][3], bo + 1 * TILE_B);
            }
            #pragma unroll
            for (int mi = 0; mi < 4; mi++)
                #pragma unroll
                for (int ni = 0; ni < 4; ni++) {
                    const int pr = ni >> 1, sl = (ni & 1) * 2;
                    mma_f16(acc[mi][ni], af[mi], bf[pr][sl], bf[pr][sl + 1]);
                }
        }
        __syncthreads();
    }

    #pragma unroll
    for (int mi = 0; mi < 4; mi++) {
        #pragma unroll
        for (int half = 0; half < 2; half++) {
            int m = m0 + wm + mi * 16 + g + half * 8;
            if (m >= N_NODES) continue;
            #pragma unroll
            for (int ni = 0; ni < 4; ni++) {
                int col = n0 + wn + ni * 8 + tg * 2;
                float v0 = acc[mi][ni][half * 2 + 0];
                float v1 = acc[mi][ni][half * 2 + 1];
                if (SEL == 0) {
                    v0 = fmaxf(v0 + __ldg(&bias[col]),     0.f);
                    v1 = fmaxf(v1 + __ldg(&bias[col + 1]), 0.f);
                    *(uint32_t*)&g_h1[(size_t)m * F_HID + col] =
                        h2_as_u32(__floats2half2_rn(v0, v1));
                } else {
                    *(float2*)&g_t2[(size_t)m * F_OUT_P + col] = make_float2(v0, v1);
                }
            }
        }
    }
}

// ---------------- layer-2: CSR gather (x2 unrolled) + bias + relu ------------
__global__ __launch_bounds__(256)
void gather2_kernel(const float* __restrict__ b2, float* __restrict__ out) {
    int node = blockIdx.x * 8 + (threadIdx.x >> 5);
    if (node >= N_NODES) return;
    int lane = threadIdx.x & 31;
    float di = g_dinv[node];
    const float4* t4 = (const float4*)g_t2;
    size_t base = (size_t)node * 64;            // 256 floats = 64 float4
    float4 a0 = t4[base + lane], a1 = t4[base + 32 + lane];
    float ws = di * di;
    a0.x *= ws; a0.y *= ws; a0.z *= ws; a0.w *= ws;
    a1.x *= ws; a1.y *= ws; a1.z *= ws; a1.w *= ws;
    int beg = g_rowbeg[node], end = beg + g_edeg[node];
    int j = beg;
    for (; j + 1 < end; j += 2) {
        int s0 = g_csrc[j], s1 = g_csrc[j + 1];
        float w0 = g_dinv[s0] * di, w1 = g_dinv[s1] * di;
        size_t p0 = (size_t)s0 * 64, p1 = (size_t)s1 * 64;
        float4 u0 = t4[p0 + lane], u1 = t4[p0 + 32 + lane];
        float4 v0 = t4[p1 + lane], v1 = t4[p1 + 32 + lane];
        a0.x += w0*u0.x + w1*v0.x; a0.y += w0*u0.y + w1*v0.y;
        a0.z += w0*u0.z + w1*v0.z; a0.w += w0*u0.w + w1*v0.w;
        a1.x += w0*u1.x + w1*v1.x; a1.y += w0*u1.y + w1*v1.y;
        a1.z += w0*u1.z + w1*v1.z; a1.w += w0*u1.w + w1*v1.w;
    }
    if (j < end) {
        int s = g_csrc[j];
        float w = g_dinv[s] * di;
        size_t p = (size_t)s * 64;
        float4 u0 = t4[p + lane], u1 = t4[p + 32 + lane];
        a0.x += w*u0.x; a0.y += w*u0.y; a0.z += w*u0.z; a0.w += w*u0.w;
        a1.x += w*u1.x; a1.y += w*u1.y; a1.z += w*u1.z; a1.w += w*u1.w;
    }
    float* orow = out + (size_t)node * F_OUT;
    int c0 = lane * 4;
    float va[4] = {a0.x, a0.y, a0.z, a0.w};
    #pragma unroll
    for (int q = 0; q < 4; q++)
        orow[c0 + q] = fmaxf(va[q] + __ldg(&b2[c0 + q]), 0.f);   // cols 0..127 < 250
    int c1 = 128 + lane * 4;
    float vb[4] = {a1.x, a1.y, a1.z, a1.w};
    #pragma unroll
    for (int q = 0; q < 4; q++) {
        int c = c1 + q;
        if (c < F_OUT) orow[c] = fmaxf(vb[q] + __ldg(&b2[c]), 0.f);
    }
}

// ---------------- launch ----------------
extern "C" void kernel_launch(void* const* d_in, const int* in_sizes, int n_in,
                              void* d_out, int out_size) {
    const float* x  = (const float*)d_in[0];
    const void*  ei = d_in[1];
    const float* W1 = (const float*)d_in[2];
    const float* b1 = (const float*)d_in[3];
    const float* W2 = (const float*)d_in[4];
    const float* b2 = (const float*)d_in[5];
    float* out = (float*)d_out;

    cudaFuncSetAttribute(gemm_mma_kernel<0, F_IN>,
                         cudaFuncAttributeMaxDynamicSharedMemorySize, GSMEM);
    cudaFuncSetAttribute(gemm_mma_kernel<1, F_HID>,
                         cudaFuncAttributeMaxDynamicSharedMemorySize, GSMEM);

    detect_init_kernel<<<INIT_NB, 256>>>(ei, W1, W2);              // 1 (init + weights)
    convert_count_kernel<<<(N_EDGES + 255) / 256, 256>>>(ei);      // 2 (count + rank)
    alloc_scan_kernel<<<SCAN_NB, SCAN_B>>>();                      // 3
    fill_kernel<<<(N_EDGES + 255) / 256, 256>>>();                 // 4 (no atomics)
    gather1_kernel<<<(N_NODES + 7) / 8, 256>>>(x);                 // 5
    {
        dim3 grid(F_HID / 128, (N_NODES + 127) / 128);             // 6: (4, 391)
        gemm_mma_kernel<0, F_IN><<<grid, 256, GSMEM>>>(b1);
    }
    {
        dim3 grid(F_OUT_P / 128, (N_NODES + 127) / 128);           // 7: (2, 391)
        gemm_mma_kernel<1, F_HID><<<grid, 256, GSMEM>>>(nullptr);
    }
    gather2_kernel<<<(N_NODES + 7) / 8, 256>>>(b2, out);           // 8
}